// round 7
// baseline (speedup 1.0000x reference)
#include <cuda_runtime.h>
#include <cuda_fp16.h>
#include <cuda_bf16.h>
#include <cstddef>

// Class-balanced triplet loss.
// Prologue: fp32 batch -> fp16 table; w_row[b] = 1/img[labels[b]].
// Main: 16 lanes per triplet (2 triplets/warp), uint4 fp16 gathers,
//       index prefetch pipeline, 8 blocks/SM, last-block-done finish.

constexpr int D        = 128;
constexpr int BMAX     = 4096;
constexpr int NBLOCKS  = 1184;  // 148 SMs * 8 resident blocks
constexpr int NTHREADS = 256;

__device__ __half       g_batch_h[(size_t)BMAX * D];   // 1 MB fp16 table
__device__ float        g_wrow[BMAX];                  // 1/img[label[b]]
__device__ float        g_partials[NBLOCKS];
__device__ unsigned int g_count = 0;                   // wraps -> graph-replay safe

__global__ void prologue_kernel(const float* __restrict__ batch,
                                const int*   __restrict__ labels,
                                const float* __restrict__ img,
                                int n4, int B)
{
    const int i = blockIdx.x * blockDim.x + threadIdx.x;
    if (i < n4) {
        const float4 v = __ldg(reinterpret_cast<const float4*>(batch) + i);
        __half2 h0 = __floats2half2_rn(v.x, v.y);
        __half2 h1 = __floats2half2_rn(v.z, v.w);
        uint2 packed;
        packed.x = *reinterpret_cast<unsigned int*>(&h0);
        packed.y = *reinterpret_cast<unsigned int*>(&h1);
        reinterpret_cast<uint2*>(g_batch_h)[i] = packed;
    }
    if (i < B) {
        g_wrow[i] = 1.0f / __ldg(&img[__ldg(&labels[i])]);
    }
}

__global__ __launch_bounds__(NTHREADS, 8)
void trip_fused_kernel(const int* __restrict__ triplets,
                       const float* __restrict__ img,
                       float* __restrict__ out,
                       int T, int C)
{
    const int lane   = threadIdx.x & 31;
    const int sub    = lane & 15;     // lane within 16-lane triplet group
    const int half_w = lane >> 4;     // which triplet of the pair
    const int wid    = threadIdx.x >> 5;
    const int gw     = blockIdx.x * (NTHREADS / 32) + wid;
    const int nw     = NBLOCKS * (NTHREADS / 32);
    const int step   = 2 * nw;

    const char* __restrict__ tbl = reinterpret_cast<const char*>(g_batch_h);

    float acc = 0.0f;

    int t0 = gw * 2;
    // ---- prime the pipeline: indices for the first pair ----
    int ia = 0, ip = 0, in_ = 0;
    {
        const int  tt = t0 + half_w;
        const int  tb = (tt < T) ? 3 * tt : 0;
        ia  = __ldg(&triplets[tb + 0]);
        ip  = __ldg(&triplets[tb + 1]);
        in_ = __ldg(&triplets[tb + 2]);
    }

    while (t0 < T) {
        const bool valid = (t0 + half_w < T);

        // 32-bit byte offsets into the 1MB table (row = 256B)
        const uint4 av = __ldg(reinterpret_cast<const uint4*>(tbl + ((unsigned)ia  << 8)) + sub);
        const uint4 pv = __ldg(reinterpret_cast<const uint4*>(tbl + ((unsigned)ip  << 8)) + sub);
        const uint4 nv = __ldg(reinterpret_cast<const uint4*>(tbl + ((unsigned)in_ << 8)) + sub);

        // ---- prefetch next iteration's indices while gathers are in flight ----
        const int t0n = t0 + step;
        int ia2, ip2, in2;
        {
            const int tt = t0n + half_w;
            const int tb = (tt < T) ? 3 * tt : 0;
            ia2 = __ldg(&triplets[tb + 0]);
            ip2 = __ldg(&triplets[tb + 1]);
            in2 = __ldg(&triplets[tb + 2]);
        }

        const __half2 a0 = *reinterpret_cast<const __half2*>(&av.x);
        const __half2 a1 = *reinterpret_cast<const __half2*>(&av.y);
        const __half2 a2 = *reinterpret_cast<const __half2*>(&av.z);
        const __half2 a3 = *reinterpret_cast<const __half2*>(&av.w);
        const __half2 p0 = *reinterpret_cast<const __half2*>(&pv.x);
        const __half2 p1 = *reinterpret_cast<const __half2*>(&pv.y);
        const __half2 p2 = *reinterpret_cast<const __half2*>(&pv.z);
        const __half2 p3 = *reinterpret_cast<const __half2*>(&pv.w);
        const __half2 n0 = *reinterpret_cast<const __half2*>(&nv.x);
        const __half2 n1 = *reinterpret_cast<const __half2*>(&nv.y);
        const __half2 n2 = *reinterpret_cast<const __half2*>(&nv.z);
        const __half2 n3 = *reinterpret_cast<const __half2*>(&nv.w);

        const __half2 d0 = __hsub2(a0, p0);
        const __half2 d1 = __hsub2(a1, p1);
        const __half2 d2 = __hsub2(a2, p2);
        const __half2 d3 = __hsub2(a3, p3);
        const __half2 e0 = __hsub2(a0, n0);
        const __half2 e1 = __hsub2(a1, n1);
        const __half2 e2 = __hsub2(a2, n2);
        const __half2 e3 = __hsub2(a3, n3);

        __half2 acc2 = __hmul2(d0, d0);
        acc2 = __hfma2(d1, d1, acc2);
        acc2 = __hfma2(d2, d2, acc2);
        acc2 = __hfma2(d3, d3, acc2);
        acc2 = __hfma2(e0, __hneg2(e0), acc2);
        acc2 = __hfma2(e1, __hneg2(e1), acc2);
        acc2 = __hfma2(e2, __hneg2(e2), acc2);
        acc2 = __hfma2(e3, __hneg2(e3), acc2);

        const float2 f = __half22float2(acc2);
        float s = f.x + f.y;

        // reduce across the 16-lane group
        s += __shfl_xor_sync(0xffffffffu, s, 8);
        s += __shfl_xor_sync(0xffffffffu, s, 4);
        s += __shfl_xor_sync(0xffffffffu, s, 2);
        s += __shfl_xor_sync(0xffffffffu, s, 1);

        if (sub == 0 && valid) {
            const float loss = s + 1.0f;   // MARGIN = 1.0
            if (loss > 0.0f) {
                acc += loss * __ldg(&g_wrow[ia]);   // wrow is L1-resident (16KB)
            }
        }

        t0 = t0n; ia = ia2; ip = ip2; in_ = in2;
    }

    // ---- warp reduce (lanes 0 and 16 hold values) ----
    acc += __shfl_down_sync(0xffffffffu, acc, 16);
    acc += __shfl_down_sync(0xffffffffu, acc, 8);
    acc += __shfl_down_sync(0xffffffffu, acc, 4);
    acc += __shfl_down_sync(0xffffffffu, acc, 2);
    acc += __shfl_down_sync(0xffffffffu, acc, 1);

    __shared__ float sacc[NTHREADS / 32];
    if (lane == 0) sacc[wid] = acc;
    __syncthreads();

    __shared__ bool s_last;
    if (threadIdx.x < (NTHREADS / 32)) {
        float v = sacc[threadIdx.x];
        v += __shfl_down_sync(0xffu, v, 4);
        v += __shfl_down_sync(0xffu, v, 2);
        v += __shfl_down_sync(0xffu, v, 1);
        if (threadIdx.x == 0) {
            g_partials[blockIdx.x] = v;
            __threadfence();
            unsigned int prev = atomicInc(&g_count, NBLOCKS - 1);
            s_last = (prev == NBLOCKS - 1);
        }
    }
    __syncthreads();

    if (s_last) {
        __shared__ float s1[NTHREADS];
        __shared__ float s2[NTHREADS];
        const int tid = threadIdx.x;

        float a = 0.0f, b = 0.0f;
        for (int i = tid; i < NBLOCKS; i += NTHREADS) a += g_partials[i];
        for (int i = tid; i < C; i += NTHREADS) b += __ldg(&img[i]);
        s1[tid] = a;
        s2[tid] = b;
        __syncthreads();

        for (int s = NTHREADS / 2; s > 0; s >>= 1) {
            if (tid < s) {
                s1[tid] += s1[tid + s];
                s2[tid] += s2[tid + s];
            }
            __syncthreads();
        }
        if (tid == 0) {
            out[0] = s1[0] * s2[0] / (float)T;   // mean, total = sum(img)
        }
    }
}

extern "C" void kernel_launch(void* const* d_in, const int* in_sizes, int n_in,
                              void* d_out, int out_size)
{
    const float* batch    = (const float*)d_in[0];
    const int*   triplets = (const int*)  d_in[1];
    const int*   labels   = (const int*)  d_in[2];
    const float* img      = (const float*)d_in[3];
    float*       out      = (float*)d_out;

    const int B  = in_sizes[2];
    const int T  = in_sizes[1] / 3;
    const int C  = in_sizes[3];
    const int n4 = in_sizes[0] / 4;

    const int pblocks = (n4 + 255) / 256;
    prologue_kernel<<<pblocks, 256>>>(batch, labels, img, n4, B);
    trip_fused_kernel<<<NBLOCKS, NTHREADS>>>(triplets, img, out, T, C);
}

// round 8
// speedup vs baseline: 1.0309x; 1.0309x over previous
#include <cuda_runtime.h>
#include <cuda_fp16.h>
#include <cuda_bf16.h>
#include <cstddef>

// Class-balanced triplet loss.
// Prologue: fp32 batch -> fp16 table; w_row[b] = 1/img[labels[b]].
// Main: 8 lanes per triplet (4 triplets/warp/iter), 2xLDG.128 per row per lane,
//       6 gathers in flight, index prefetch, 3-shuffle reduce, last-block finish.

constexpr int D        = 128;
constexpr int BMAX     = 4096;
constexpr int NBLOCKS  = 888;   // 148 SMs * 6 resident blocks
constexpr int NTHREADS = 256;

__device__ __half       g_batch_h[(size_t)BMAX * D];   // 1 MB fp16 table
__device__ float        g_wrow[BMAX];                  // 1/img[label[b]]
__device__ float        g_partials[NBLOCKS];
__device__ unsigned int g_count = 0;                   // wraps -> graph-replay safe

__global__ void prologue_kernel(const float* __restrict__ batch,
                                const int*   __restrict__ labels,
                                const float* __restrict__ img,
                                int n4, int B)
{
    const int i = blockIdx.x * blockDim.x + threadIdx.x;
    if (i < n4) {
        const float4 v = __ldg(reinterpret_cast<const float4*>(batch) + i);
        __half2 h0 = __floats2half2_rn(v.x, v.y);
        __half2 h1 = __floats2half2_rn(v.z, v.w);
        uint2 packed;
        packed.x = *reinterpret_cast<unsigned int*>(&h0);
        packed.y = *reinterpret_cast<unsigned int*>(&h1);
        reinterpret_cast<uint2*>(g_batch_h)[i] = packed;
    }
    if (i < B) {
        g_wrow[i] = 1.0f / __ldg(&img[__ldg(&labels[i])]);
    }
}

__device__ __forceinline__ void sq_diff_acc(const uint4& x, const uint4& y,
                                            __half2& accum)
{
    const __half2 x0 = *reinterpret_cast<const __half2*>(&x.x);
    const __half2 x1 = *reinterpret_cast<const __half2*>(&x.y);
    const __half2 x2 = *reinterpret_cast<const __half2*>(&x.z);
    const __half2 x3 = *reinterpret_cast<const __half2*>(&x.w);
    const __half2 y0 = *reinterpret_cast<const __half2*>(&y.x);
    const __half2 y1 = *reinterpret_cast<const __half2*>(&y.y);
    const __half2 y2 = *reinterpret_cast<const __half2*>(&y.z);
    const __half2 y3 = *reinterpret_cast<const __half2*>(&y.w);
    const __half2 d0 = __hsub2(x0, y0);
    const __half2 d1 = __hsub2(x1, y1);
    const __half2 d2 = __hsub2(x2, y2);
    const __half2 d3 = __hsub2(x3, y3);
    accum = __hfma2(d0, d0, accum);
    accum = __hfma2(d1, d1, accum);
    accum = __hfma2(d2, d2, accum);
    accum = __hfma2(d3, d3, accum);
}

__global__ __launch_bounds__(NTHREADS, 6)
void trip_fused_kernel(const int* __restrict__ triplets,
                       const float* __restrict__ img,
                       float* __restrict__ out,
                       int T, int C)
{
    const int lane = threadIdx.x & 31;
    const int sg   = lane >> 3;       // subgroup 0..3 -> which triplet of the quad
    const int sub  = lane & 7;        // lane within 8-lane triplet group
    const int wid  = threadIdx.x >> 5;
    const int gw   = blockIdx.x * (NTHREADS / 32) + wid;
    const int nw   = NBLOCKS * (NTHREADS / 32);
    const int step = 4 * nw;

    const char* __restrict__ tbl = reinterpret_cast<const char*>(g_batch_h);

    float acc = 0.0f;

    int t0 = gw * 4;
    // ---- prime: indices for the first quad (per-lane, by subgroup) ----
    int ia, ip, in_;
    {
        const int tt = t0 + sg;
        const int tb = (tt < T) ? 3 * tt : 0;
        ia  = __ldg(&triplets[tb + 0]);
        ip  = __ldg(&triplets[tb + 1]);
        in_ = __ldg(&triplets[tb + 2]);
    }

    while (t0 < T) {
        const bool valid = (t0 + sg < T);

        // six 16B gathers in flight: each 8-lane group covers one 256B row
        const uint4* __restrict__ A = reinterpret_cast<const uint4*>(tbl + ((unsigned)ia  << 8));
        const uint4* __restrict__ P = reinterpret_cast<const uint4*>(tbl + ((unsigned)ip  << 8));
        const uint4* __restrict__ N = reinterpret_cast<const uint4*>(tbl + ((unsigned)in_ << 8));
        const uint4 av0 = __ldg(A + sub);
        const uint4 av1 = __ldg(A + sub + 8);
        const uint4 pv0 = __ldg(P + sub);
        const uint4 pv1 = __ldg(P + sub + 8);
        const uint4 nv0 = __ldg(N + sub);
        const uint4 nv1 = __ldg(N + sub + 8);

        // ---- prefetch next quad's indices while gathers fly ----
        const int t0n = t0 + step;
        int ia2, ip2, in2;
        {
            const int tt = t0n + sg;
            const int tb = (tt < T) ? 3 * tt : 0;
            ia2 = __ldg(&triplets[tb + 0]);
            ip2 = __ldg(&triplets[tb + 1]);
            in2 = __ldg(&triplets[tb + 2]);
        }

        __half2 accP = __float2half2_rn(0.0f);
        __half2 accN = __float2half2_rn(0.0f);
        sq_diff_acc(av0, pv0, accP);
        sq_diff_acc(av1, pv1, accP);
        sq_diff_acc(av0, nv0, accN);
        sq_diff_acc(av1, nv1, accN);

        const float2 fP = __half22float2(accP);
        const float2 fN = __half22float2(accN);
        float s = (fP.x + fP.y) - (fN.x + fN.y);

        // reduce across the 8-lane group (3 shuffles for all 4 triplets at once)
        s += __shfl_xor_sync(0xffffffffu, s, 4);
        s += __shfl_xor_sync(0xffffffffu, s, 2);
        s += __shfl_xor_sync(0xffffffffu, s, 1);

        if (sub == 0 && valid) {
            const float loss = s + 1.0f;   // MARGIN = 1.0
            if (loss > 0.0f) {
                acc += loss * __ldg(&g_wrow[ia]);   // wrow is L1-resident (16KB)
            }
        }

        t0 = t0n; ia = ia2; ip = ip2; in_ = in2;
    }

    // ---- warp reduce (lanes 0,8,16,24 hold values; others are 0) ----
    acc += __shfl_xor_sync(0xffffffffu, acc, 16);
    acc += __shfl_xor_sync(0xffffffffu, acc, 8);

    __shared__ float sacc[NTHREADS / 32];
    if (lane == 0) sacc[wid] = acc;
    __syncthreads();

    __shared__ bool s_last;
    if (threadIdx.x < (NTHREADS / 32)) {
        float v = sacc[threadIdx.x];
        v += __shfl_down_sync(0xffu, v, 4);
        v += __shfl_down_sync(0xffu, v, 2);
        v += __shfl_down_sync(0xffu, v, 1);
        if (threadIdx.x == 0) {
            g_partials[blockIdx.x] = v;
            __threadfence();
            unsigned int prev = atomicInc(&g_count, NBLOCKS - 1);
            s_last = (prev == NBLOCKS - 1);
        }
    }
    __syncthreads();

    if (s_last) {
        __shared__ float s1[NTHREADS];
        __shared__ float s2[NTHREADS];
        const int tid = threadIdx.x;

        float a = 0.0f, b = 0.0f;
        for (int i = tid; i < NBLOCKS; i += NTHREADS) a += g_partials[i];
        for (int i = tid; i < C; i += NTHREADS) b += __ldg(&img[i]);
        s1[tid] = a;
        s2[tid] = b;
        __syncthreads();

        for (int s = NTHREADS / 2; s > 0; s >>= 1) {
            if (tid < s) {
                s1[tid] += s1[tid + s];
                s2[tid] += s2[tid + s];
            }
            __syncthreads();
        }
        if (tid == 0) {
            out[0] = s1[0] * s2[0] / (float)T;   // mean, total = sum(img)
        }
    }
}

extern "C" void kernel_launch(void* const* d_in, const int* in_sizes, int n_in,
                              void* d_out, int out_size)
{
    const float* batch    = (const float*)d_in[0];
    const int*   triplets = (const int*)  d_in[1];
    const int*   labels   = (const int*)  d_in[2];
    const float* img      = (const float*)d_in[3];
    float*       out      = (float*)d_out;

    const int B  = in_sizes[2];
    const int T  = in_sizes[1] / 3;
    const int C  = in_sizes[3];
    const int n4 = in_sizes[0] / 4;

    const int pblocks = (n4 + 255) / 256;
    prologue_kernel<<<pblocks, 256>>>(batch, labels, img, n4, B);
    trip_fused_kernel<<<NBLOCKS, NTHREADS>>>(triplets, img, out, T, C);
}